// round 8
// baseline (speedup 1.0000x reference)
#include <cuda_runtime.h>

// Scratch: expanded gate table (100 experts x 240 dims). Device global => no allocation.
__device__ __align__(16) float g_gates_full[100 * 240];

// ---------------------------------------------------------------------------
// Kernel A: tiny MLP over 100 expert embeddings, then irreps-expand to 240.
// One block per expert, 256 threads (one per hidden unit).
// ---------------------------------------------------------------------------
__global__ void gates_kernel(const float* __restrict__ e_feat,
                             const float* __restrict__ W1, const float* __restrict__ b1,
                             const float* __restrict__ W2, const float* __restrict__ b2,
                             const float* __restrict__ W3, const float* __restrict__ b3) {
    const int e = blockIdx.x;   // 0..99
    const int t = threadIdx.x;  // 0..255

    __shared__ float se[64];
    __shared__ float h1[256];
    __shared__ float h2[256];
    __shared__ float gt[112];

    if (t < 64) se[t] = e_feat[e * 64 + t];
    __syncthreads();

    // Layer 1: (64 -> 256), relu
    float acc = b1[t];
#pragma unroll 8
    for (int k = 0; k < 64; ++k)
        acc = fmaf(se[k], W1[k * 256 + t], acc);
    h1[t] = fmaxf(acc, 0.0f);
    __syncthreads();

    // Layer 2: (256 -> 256), relu
    acc = b2[t];
#pragma unroll 8
    for (int k = 0; k < 256; ++k)
        acc = fmaf(h1[k], W2[k * 256 + t], acc);
    h2[t] = fmaxf(acc, 0.0f);
    __syncthreads();

    // Layer 3: (256 -> 112), no activation
    if (t < 112) {
        acc = b3[t];
#pragma unroll 8
        for (int k = 0; k < 256; ++k)
            acc = fmaf(h2[k], W3[k * 112 + t], acc);
        gt[t] = acc;
    }
    __syncthreads();

    // Irreps expansion: IRREPS = [(64,1),(32,3),(16,5)] -> 240 dims, 112 gates
    if (t < 240) {
        int idx;
        if (t < 64)       idx = t;                       // mul=64, dim=1
        else if (t < 160) idx = 64 + (t - 64) / 3;       // mul=32, dim=3
        else              idx = 96 + (t - 160) / 5;      // mul=16, dim=5
        g_gates_full[e * 240 + t] = gt[idx];
    }
}

// ---------------------------------------------------------------------------
// Kernel B: out[m, e, d] = x[m, d] * gates_full[e, d]
// One block per m-row. Stage x row (240 f32 = 60 float4) in shared; stream
// 6000 float4 stores per block. Gate table (96KB) is L1-resident after warmup.
// ---------------------------------------------------------------------------
__global__ void modulate_kernel(const float* __restrict__ x,
                                float* __restrict__ out) {
    const int m = blockIdx.x;   // 0..4095
    const int t = threadIdx.x;  // 0..255

    __shared__ float4 xs[60];
    if (t < 60)
        xs[t] = reinterpret_cast<const float4*>(x + (size_t)m * 240)[t];
    __syncthreads();

    const float4* __restrict__ g4 = reinterpret_cast<const float4*>(g_gates_full);
    float4* __restrict__ o4 = reinterpret_cast<float4*>(out) + (size_t)m * 6000;

    // For float4 index j, element base is 4j; (4j) % 240 = 4*(j % 60).
    int d4 = t % 60;
#pragma unroll 4
    for (int j = t; j < 6000; j += 256) {
        float4 g = g4[j];
        float4 xv = xs[d4];
        float4 r;
        r.x = xv.x * g.x;
        r.y = xv.y * g.y;
        r.z = xv.z * g.z;
        r.w = xv.w * g.w;
        o4[j] = r;
        d4 += 16;               // (j += 256) -> (d4 += 256 % 60 = 16) mod 60
        if (d4 >= 60) d4 -= 60;
    }
}

// ---------------------------------------------------------------------------
// Launch. Input order (metadata): x, e_feat, W1, b1, W2, b2, W3, b3
// ---------------------------------------------------------------------------
extern "C" void kernel_launch(void* const* d_in, const int* in_sizes, int n_in,
                              void* d_out, int out_size) {
    const float* x      = (const float*)d_in[0];
    const float* e_feat = (const float*)d_in[1];
    const float* W1     = (const float*)d_in[2];
    const float* b1     = (const float*)d_in[3];
    const float* W2     = (const float*)d_in[4];
    const float* b2     = (const float*)d_in[5];
    const float* W3     = (const float*)d_in[6];
    const float* b3     = (const float*)d_in[7];
    float* out          = (float*)d_out;

    gates_kernel<<<100, 256>>>(e_feat, W1, b1, W2, b2, W3, b3);
    modulate_kernel<<<4096, 256>>>(x, out);
}

// round 9
// speedup vs baseline: 1.3605x; 1.3605x over previous
#include <cuda_runtime.h>

// Scratch: expanded gate table (100 experts x 240 dims). Device global => no allocation.
__device__ __align__(16) float g_gates_full[100 * 240];

// ---------------------------------------------------------------------------
// Kernel A: tiny MLP over 100 expert embeddings, then irreps-expand to 240.
// One block per expert, 256 threads (one per hidden unit).
// ---------------------------------------------------------------------------
__global__ void gates_kernel(const float* __restrict__ e_feat,
                             const float* __restrict__ W1, const float* __restrict__ b1,
                             const float* __restrict__ W2, const float* __restrict__ b2,
                             const float* __restrict__ W3, const float* __restrict__ b3) {
    const int e = blockIdx.x;   // 0..99
    const int t = threadIdx.x;  // 0..255

    __shared__ float se[64];
    __shared__ float h1[256];
    __shared__ float h2[256];
    __shared__ float gt[112];

    if (t < 64) se[t] = e_feat[e * 64 + t];
    __syncthreads();

    // Layer 1: (64 -> 256), relu
    float acc = b1[t];
#pragma unroll 8
    for (int k = 0; k < 64; ++k)
        acc = fmaf(se[k], W1[k * 256 + t], acc);
    h1[t] = fmaxf(acc, 0.0f);
    __syncthreads();

    // Layer 2: (256 -> 256), relu
    acc = b2[t];
#pragma unroll 8
    for (int k = 0; k < 256; ++k)
        acc = fmaf(h1[k], W2[k * 256 + t], acc);
    h2[t] = fmaxf(acc, 0.0f);
    __syncthreads();

    // Layer 3: (256 -> 112), no activation
    if (t < 112) {
        acc = b3[t];
#pragma unroll 8
        for (int k = 0; k < 256; ++k)
            acc = fmaf(h2[k], W3[k * 112 + t], acc);
        gt[t] = acc;
    }
    __syncthreads();

    // Irreps expansion: IRREPS = [(64,1),(32,3),(16,5)] -> 240 dims, 112 gates
    if (t < 240) {
        int idx;
        if (t < 64)       idx = t;                       // mul=64, dim=1
        else if (t < 160) idx = 64 + (t - 64) / 3;       // mul=32, dim=3
        else              idx = 96 + (t - 160) / 5;      // mul=16, dim=5
        g_gates_full[e * 240 + t] = gt[idx];
    }
}

// ---------------------------------------------------------------------------
// Kernel B: out[m, e, d] = x[m, d] * gates_full[e, d]
// TWO m-rows per block: each gate float4 is loaded once and used for 2 rows
// (halves L1 gate-load traffic per store). Output stores use __stcs
// (streaming / evict-first) since the 393MB output is write-once.
// ---------------------------------------------------------------------------
__global__ void modulate_kernel(const float* __restrict__ x,
                                float* __restrict__ out) {
    const int m0 = blockIdx.x * 2;  // 0,2,...,4094
    const int t  = threadIdx.x;     // 0..255

    __shared__ float4 xs0[60];
    __shared__ float4 xs1[60];
    if (t < 60)
        xs0[t] = reinterpret_cast<const float4*>(x + (size_t)m0 * 240)[t];
    else if (t >= 64 && t < 124)
        xs1[t - 64] = reinterpret_cast<const float4*>(x + (size_t)(m0 + 1) * 240)[t - 64];
    __syncthreads();

    const float4* __restrict__ g4 = reinterpret_cast<const float4*>(g_gates_full);
    float4* __restrict__ o0 = reinterpret_cast<float4*>(out) + (size_t)m0 * 6000;
    float4* __restrict__ o1 = o0 + 6000;

    // For float4 index j, element base is 4j; (4j) % 240 = 4*(j % 60).
    int d4 = t % 60;
#pragma unroll 4
    for (int j = t; j < 6000; j += 256) {
        float4 g  = g4[j];
        float4 a  = xs0[d4];
        float4 b  = xs1[d4];
        float4 r0, r1;
        r0.x = a.x * g.x; r0.y = a.y * g.y; r0.z = a.z * g.z; r0.w = a.w * g.w;
        r1.x = b.x * g.x; r1.y = b.y * g.y; r1.z = b.z * g.z; r1.w = b.w * g.w;
        __stcs(o0 + j, r0);
        __stcs(o1 + j, r1);
        d4 += 16;               // (j += 256) -> (d4 += 256 % 60 = 16) mod 60
        if (d4 >= 60) d4 -= 60;
    }
}

// ---------------------------------------------------------------------------
// Launch. Input order (metadata): x, e_feat, W1, b1, W2, b2, W3, b3
// ---------------------------------------------------------------------------
extern "C" void kernel_launch(void* const* d_in, const int* in_sizes, int n_in,
                              void* d_out, int out_size) {
    const float* x      = (const float*)d_in[0];
    const float* e_feat = (const float*)d_in[1];
    const float* W1     = (const float*)d_in[2];
    const float* b1     = (const float*)d_in[3];
    const float* W2     = (const float*)d_in[4];
    const float* b2     = (const float*)d_in[5];
    const float* W3     = (const float*)d_in[6];
    const float* b3     = (const float*)d_in[7];
    float* out          = (float*)d_out;

    gates_kernel<<<100, 256>>>(e_feat, W1, b1, W2, b2, W3, b3);
    modulate_kernel<<<2048, 256>>>(x, out);
}

// round 10
// speedup vs baseline: 1.3743x; 1.0102x over previous
#include <cuda_runtime.h>

// Scratch: expanded gate table (100 experts x 240 dims). Device global => no allocation.
__device__ __align__(16) float g_gates_full[100 * 240];

// ---------------------------------------------------------------------------
// Kernel A: tiny MLP over 100 expert embeddings, then irreps-expand to 240.
// One block per expert, 256 threads (one per hidden unit).
// 4 partial accumulators break the serial FMA chain so the streamed W loads
// overlap with compute.
// ---------------------------------------------------------------------------
__global__ void gates_kernel(const float* __restrict__ e_feat,
                             const float* __restrict__ W1, const float* __restrict__ b1,
                             const float* __restrict__ W2, const float* __restrict__ b2,
                             const float* __restrict__ W3, const float* __restrict__ b3) {
    const int e = blockIdx.x;   // 0..99
    const int t = threadIdx.x;  // 0..255

    __shared__ float se[64];
    __shared__ float h1[256];
    __shared__ float h2[256];
    __shared__ float gt[112];

    if (t < 64) se[t] = e_feat[e * 64 + t];
    __syncthreads();

    // Layer 1: (64 -> 256), relu. 4 partial accumulators.
    {
        float a0 = 0.f, a1 = 0.f, a2 = 0.f, a3 = 0.f;
#pragma unroll
        for (int k = 0; k < 64; k += 4) {
            a0 = fmaf(se[k + 0], W1[(k + 0) * 256 + t], a0);
            a1 = fmaf(se[k + 1], W1[(k + 1) * 256 + t], a1);
            a2 = fmaf(se[k + 2], W1[(k + 2) * 256 + t], a2);
            a3 = fmaf(se[k + 3], W1[(k + 3) * 256 + t], a3);
        }
        h1[t] = fmaxf(b1[t] + ((a0 + a1) + (a2 + a3)), 0.0f);
    }
    __syncthreads();

    // Layer 2: (256 -> 256), relu. 4 partial accumulators.
    {
        float a0 = 0.f, a1 = 0.f, a2 = 0.f, a3 = 0.f;
#pragma unroll 8
        for (int k = 0; k < 256; k += 4) {
            a0 = fmaf(h1[k + 0], W2[(k + 0) * 256 + t], a0);
            a1 = fmaf(h1[k + 1], W2[(k + 1) * 256 + t], a1);
            a2 = fmaf(h1[k + 2], W2[(k + 2) * 256 + t], a2);
            a3 = fmaf(h1[k + 3], W2[(k + 3) * 256 + t], a3);
        }
        h2[t] = fmaxf(b2[t] + ((a0 + a1) + (a2 + a3)), 0.0f);
    }
    __syncthreads();

    // Layer 3: (256 -> 112), no activation. 4 partial accumulators.
    if (t < 112) {
        float a0 = 0.f, a1 = 0.f, a2 = 0.f, a3 = 0.f;
#pragma unroll 8
        for (int k = 0; k < 256; k += 4) {
            a0 = fmaf(h2[k + 0], W3[(k + 0) * 112 + t], a0);
            a1 = fmaf(h2[k + 1], W3[(k + 1) * 112 + t], a1);
            a2 = fmaf(h2[k + 2], W3[(k + 2) * 112 + t], a2);
            a3 = fmaf(h2[k + 3], W3[(k + 3) * 112 + t], a3);
        }
        gt[t] = b3[t] + ((a0 + a1) + (a2 + a3));
    }
    __syncthreads();

    // Irreps expansion: IRREPS = [(64,1),(32,3),(16,5)] -> 240 dims, 112 gates
    if (t < 240) {
        int idx;
        if (t < 64)       idx = t;                       // mul=64, dim=1
        else if (t < 160) idx = 64 + (t - 64) / 3;       // mul=32, dim=3
        else              idx = 96 + (t - 160) / 5;      // mul=16, dim=5
        g_gates_full[e * 240 + t] = gt[idx];
    }
}

// ---------------------------------------------------------------------------
// Kernel B: out[m, e, d] = x[m, d] * gates_full[e, d]
// FOUR m-rows per block: each gate float4 is loaded once and used for 4 rows
// (quarters L1 gate-load traffic per store). Output stores use __stcs
// (streaming / evict-first) since the 393MB output is write-once.
// ---------------------------------------------------------------------------
__global__ void modulate_kernel(const float* __restrict__ x,
                                float* __restrict__ out) {
    const int m0 = blockIdx.x * 4;  // 0,4,...,4092
    const int t  = threadIdx.x;     // 0..255

    __shared__ float4 xs[4][60];
    {
        // 240 float4 to load (4 rows x 60); thread t<240 loads one.
        if (t < 240) {
            int r = t / 60, c = t % 60;
            xs[r][c] = reinterpret_cast<const float4*>(x + (size_t)(m0 + r) * 240)[c];
        }
    }
    __syncthreads();

    const float4* __restrict__ g4 = reinterpret_cast<const float4*>(g_gates_full);
    float4* __restrict__ o0 = reinterpret_cast<float4*>(out) + (size_t)m0 * 6000;

    // For float4 index j, element base is 4j; (4j) % 240 = 4*(j % 60).
    int d4 = t % 60;
#pragma unroll 4
    for (int j = t; j < 6000; j += 256) {
        float4 g  = g4[j];
        float4 a0 = xs[0][d4];
        float4 a1 = xs[1][d4];
        float4 a2 = xs[2][d4];
        float4 a3 = xs[3][d4];
        float4 r;
        r.x = a0.x * g.x; r.y = a0.y * g.y; r.z = a0.z * g.z; r.w = a0.w * g.w;
        __stcs(o0 + j, r);
        r.x = a1.x * g.x; r.y = a1.y * g.y; r.z = a1.z * g.z; r.w = a1.w * g.w;
        __stcs(o0 + 6000 + j, r);
        r.x = a2.x * g.x; r.y = a2.y * g.y; r.z = a2.z * g.z; r.w = a2.w * g.w;
        __stcs(o0 + 12000 + j, r);
        r.x = a3.x * g.x; r.y = a3.y * g.y; r.z = a3.z * g.z; r.w = a3.w * g.w;
        __stcs(o0 + 18000 + j, r);
        d4 += 16;               // (j += 256) -> (d4 += 256 % 60 = 16) mod 60
        if (d4 >= 60) d4 -= 60;
    }
}

// ---------------------------------------------------------------------------
// Launch. Input order (metadata): x, e_feat, W1, b1, W2, b2, W3, b3
// ---------------------------------------------------------------------------
extern "C" void kernel_launch(void* const* d_in, const int* in_sizes, int n_in,
                              void* d_out, int out_size) {
    const float* x      = (const float*)d_in[0];
    const float* e_feat = (const float*)d_in[1];
    const float* W1     = (const float*)d_in[2];
    const float* b1     = (const float*)d_in[3];
    const float* W2     = (const float*)d_in[4];
    const float* b2     = (const float*)d_in[5];
    const float* W3     = (const float*)d_in[6];
    const float* b3     = (const float*)d_in[7];
    float* out          = (float*)d_out;

    gates_kernel<<<100, 256>>>(e_feat, W1, b1, W2, b2, W3, b3);
    modulate_kernel<<<1024, 256>>>(x, out);
}